// round 2
// baseline (speedup 1.0000x reference)
#include <cuda_runtime.h>

#define N_NODES 50000
#define N_EDGES 1600000
#define ND 64
#define HD 128
#define ED 32
#define MI 160
#define EB 4
#define NWARPS 16
#define THREADS (NWARPS * 32)
#define FULLMASK 0xffffffffu

// Scratch (no cudaMalloc allowed): packed int32 edge indices + dtype flag.
__device__ int g_is64;
__device__ int g_src[N_EDGES];
__device__ int g_dst[N_EDGES];

// ---------------------------------------------------------------------------
// Detect whether edge_index is int64 or int32. Indices are in [0, 50000), so
// if the buffer is int64 every high 32-bit word is 0. If it is int32, the
// sampled words are random indices; all-64-zero has probability ~(2e-5)^64.
// ---------------------------------------------------------------------------
__global__ void detect_kernel(const unsigned int* __restrict__ w) {
    if (blockIdx.x == 0 && threadIdx.x == 0) {
        int is64 = 1;
        for (int i = 0; i < 64; i++) {
            if (w[2 * i + 1] != 0u) { is64 = 0; break; }
        }
        g_is64 = is64;
    }
}

__global__ void convert_kernel(const void* __restrict__ p) {
    int i = blockIdx.x * blockDim.x + threadIdx.x;
    if (i >= N_EDGES) return;
    if (g_is64) {
        const long long* q = (const long long*)p;
        g_src[i] = (int)q[i];
        g_dst[i] = (int)q[N_EDGES + i];
    } else {
        const int* q = (const int*)p;
        g_src[i] = q[i];
        g_dst[i] = q[N_EDGES + i];
    }
}

// out = [h (N*64) | x (N*3)], initialized with the residual inputs.
__global__ void init_out_kernel(const float* __restrict__ h,
                                const float* __restrict__ x,
                                float* __restrict__ out) {
    int i = blockIdx.x * blockDim.x + threadIdx.x;
    const int nh = N_NODES * ND;
    const int total = nh + N_NODES * 3;
    if (i < nh) out[i] = h[i];
    else if (i < total) out[i] = x[i - nh];
}

__device__ __forceinline__ float silu(float v) {
    return __fdividef(v, 1.0f + __expf(-v));
}

// ---------------------------------------------------------------------------
// Main kernel: persistent grid, 1 CTA/SM (198KB smem), 16 warps/CTA.
// Each warp processes EB=4 edges per task:
//   - edge MLP via lane-parallel (32 = EDGE_DIM) compute + shfl broadcast
//   - hidden = silu(m_input @ W1 + b1) for node & coord paths, accumulated in
//     registers (j = lane + 32r), m_input broadcast via shfl from registers
//   - out = silu-hidden @ W2 + b2 via shfl broadcast
//   - coord scalar via warp reduction; scatter with atomicAdd
// ---------------------------------------------------------------------------
__global__ void __launch_bounds__(THREADS, 1)
edge_kernel(const float* __restrict__ h, const float* __restrict__ x,
            const float* __restrict__ edge_dist,
            const float* __restrict__ node_w1, const float* __restrict__ node_b1,
            const float* __restrict__ node_w2, const float* __restrict__ node_b2,
            const float* __restrict__ coord_w1, const float* __restrict__ coord_b1,
            const float* __restrict__ coord_w2,
            const float* __restrict__ edge_w1, const float* __restrict__ edge_b1,
            const float* __restrict__ edge_w2, const float* __restrict__ edge_b2,
            float* __restrict__ out) {
    extern __shared__ float smem[];
    float* s_nw1 = smem;                  // 160*128
    float* s_cw1 = s_nw1 + MI * HD;       // 160*128
    float* s_nw2 = s_cw1 + MI * HD;       // 128*64
    float* s_ew2 = s_nw2 + HD * ND;       // 32*32
    float* s_cw2 = s_ew2 + ED * ED;       // 128
    float* s_nb1 = s_cw2 + HD;            // 128
    float* s_cb1 = s_nb1 + HD;            // 128
    float* s_nb2 = s_cb1 + HD;            // 64
    float* s_ew1 = s_nb2 + ND;            // 32
    float* s_eb1 = s_ew1 + ED;            // 32
    float* s_eb2 = s_eb1 + ED;            // 32

    const int tid = threadIdx.x;
    for (int i = tid; i < MI * HD; i += THREADS) {
        s_nw1[i] = node_w1[i];
        s_cw1[i] = coord_w1[i];
    }
    for (int i = tid; i < HD * ND; i += THREADS) s_nw2[i] = node_w2[i];
    for (int i = tid; i < ED * ED; i += THREADS) s_ew2[i] = edge_w2[i];
    if (tid < HD) {
        s_cw2[tid] = coord_w2[tid];
        s_nb1[tid] = node_b1[tid];
        s_cb1[tid] = coord_b1[tid];
    }
    if (tid < ND) s_nb2[tid] = node_b2[tid];
    if (tid < ED) {
        s_ew1[tid] = edge_w1[tid];
        s_eb1[tid] = edge_b1[tid];
        s_eb2[tid] = edge_b2[tid];
    }
    __syncthreads();

    const int lane = tid & 31;
    const int warp = tid >> 5;
    const int gwarp = blockIdx.x * NWARPS + warp;
    const int nwarps_total = gridDim.x * NWARPS;
    const int ntasks = (N_EDGES + EB - 1) / EB;

    float* out_h = out;
    float* out_x = out + (size_t)N_NODES * ND;

    for (int task = gwarp; task < ntasks; task += nwarps_total) {
        const int ebase = task * EB;

        int src[EB], dst[EB];
        float dist[EB];
        bool val[EB];
#pragma unroll
        for (int i = 0; i < EB; i++) {
            int e = ebase + i;
            val[i] = (e < N_EDGES);
            int ec = val[i] ? e : 0;
            src[i] = g_src[ec];
            dst[i] = g_dst[ec];
            dist[i] = edge_dist[ec];
        }

        // ---- edge MLP: silu(d*W1 + b1) @ W2 + b2  (lane = edge-dim index)
        float ea[EB];
#pragma unroll
        for (int i = 0; i < EB; i++) {
            float t = silu(fmaf(dist[i], s_ew1[lane], s_eb1[lane]));
            float acc = s_eb2[lane];
#pragma unroll
            for (int k = 0; k < ED; k++) {
                float tv = __shfl_sync(FULLMASK, t, k);
                acc = fmaf(tv, s_ew2[k * ED + lane], acc);
            }
            ea[i] = acc;
        }

        // ---- m_input in registers: mi[i][seg] holds m_input[seg*32 + lane]
        float mi[EB][5];
#pragma unroll
        for (int i = 0; i < EB; i++) {
            const float* hs = h + (size_t)src[i] * ND;
            const float* hd = h + (size_t)dst[i] * ND;
            mi[i][0] = hs[lane];
            mi[i][1] = hs[32 + lane];
            mi[i][2] = hd[lane];
            mi[i][3] = hd[32 + lane];
            mi[i][4] = ea[i];
        }

        // ---- hidden layers (node & coord), j = lane + 32*r
        float an[EB][4], ac[EB][4];
#pragma unroll
        for (int i = 0; i < EB; i++)
#pragma unroll
            for (int r = 0; r < 4; r++) {
                an[i][r] = s_nb1[lane + 32 * r];
                ac[i][r] = s_cb1[lane + 32 * r];
            }

#pragma unroll
        for (int seg = 0; seg < 5; seg++) {
#pragma unroll
            for (int kk = 0; kk < 32; kk++) {
                const int k = seg * 32 + kk;
                const float* wnr = s_nw1 + k * HD + lane;
                const float* wcr = s_cw1 + k * HD + lane;
                float wn0 = wnr[0], wn1 = wnr[32], wn2 = wnr[64], wn3 = wnr[96];
                float wc0 = wcr[0], wc1 = wcr[32], wc2 = wcr[64], wc3 = wcr[96];
#pragma unroll
                for (int i = 0; i < EB; i++) {
                    float v = __shfl_sync(FULLMASK, mi[i][seg], kk);
                    an[i][0] = fmaf(v, wn0, an[i][0]);
                    an[i][1] = fmaf(v, wn1, an[i][1]);
                    an[i][2] = fmaf(v, wn2, an[i][2]);
                    an[i][3] = fmaf(v, wn3, an[i][3]);
                    ac[i][0] = fmaf(v, wc0, ac[i][0]);
                    ac[i][1] = fmaf(v, wc1, ac[i][1]);
                    ac[i][2] = fmaf(v, wc2, ac[i][2]);
                    ac[i][3] = fmaf(v, wc3, ac[i][3]);
                }
            }
        }

        // ---- silu on hidden
        float sn[EB][4], sc[EB][4];
#pragma unroll
        for (int i = 0; i < EB; i++)
#pragma unroll
            for (int r = 0; r < 4; r++) {
                sn[i][r] = silu(an[i][r]);
                sc[i][r] = silu(ac[i][r]);
            }

        // ---- node out: o[j] = sum_h sn[h] * W2[h][j] + b2, j = lane + 32*p
        float o[EB][2];
#pragma unroll
        for (int i = 0; i < EB; i++) {
            o[i][0] = s_nb2[lane];
            o[i][1] = s_nb2[lane + 32];
        }
#pragma unroll
        for (int hr = 0; hr < 4; hr++) {
#pragma unroll
            for (int hh = 0; hh < 32; hh++) {
                const int hidx = hr * 32 + hh;
                float w0 = s_nw2[hidx * ND + lane];
                float w1 = s_nw2[hidx * ND + lane + 32];
#pragma unroll
                for (int i = 0; i < EB; i++) {
                    float hv = __shfl_sync(FULLMASK, sn[i][hr], hh);
                    o[i][0] = fmaf(hv, w0, o[i][0]);
                    o[i][1] = fmaf(hv, w1, o[i][1]);
                }
            }
        }

        // ---- coord scalar: cw = sum_h sc[h] * coord_w2[h]  (warp reduction)
        float cw[EB];
#pragma unroll
        for (int i = 0; i < EB; i++) {
            float p = 0.0f;
#pragma unroll
            for (int r = 0; r < 4; r++)
                p = fmaf(sc[i][r], s_cw2[lane + 32 * r], p);
#pragma unroll
            for (int off = 16; off >= 1; off >>= 1)
                p += __shfl_xor_sync(FULLMASK, p, off);
            cw[i] = p;  // all lanes hold the full sum
        }

        // ---- scatter h_agg (64 floats per edge across the warp)
#pragma unroll
        for (int i = 0; i < EB; i++) {
            if (val[i]) {
                float* dsth = out_h + (size_t)dst[i] * ND;
                atomicAdd(dsth + lane, o[i][0]);
                atomicAdd(dsth + lane + 32, o[i][1]);
            }
        }

        // ---- scatter x_agg: lanes 0..EB-1 handle one edge each
        if (lane < EB) {
            int si = src[0], di = dst[0];
            float cwi = cw[0];
            bool vi = val[0];
#pragma unroll
            for (int q = 1; q < EB; q++) {
                if (lane == q) { si = src[q]; di = dst[q]; cwi = cw[q]; vi = val[q]; }
            }
            if (vi) {
                const float* xs = x + (size_t)si * 3;
                const float* xd = x + (size_t)di * 3;
                float dx = xs[0] - xd[0];
                float dy = xs[1] - xd[1];
                float dz = xs[2] - xd[2];
                float len = fmaxf(sqrtf(dx * dx + dy * dy + dz * dz), 1e-8f);
                float s = __fdividef(cwi, len);
                float* dstx = out_x + (size_t)di * 3;
                atomicAdd(dstx + 0, s * dx);
                atomicAdd(dstx + 1, s * dy);
                atomicAdd(dstx + 2, s * dz);
            }
        }
    }
}

// ---------------------------------------------------------------------------
extern "C" void kernel_launch(void* const* d_in, const int* in_sizes, int n_in,
                              void* d_out, int out_size) {
    const float* h        = (const float*)d_in[0];
    const float* x        = (const float*)d_in[1];
    const void*  eidx     = d_in[2];
    const float* edist    = (const float*)d_in[3];
    const float* node_w1  = (const float*)d_in[4];
    const float* node_b1  = (const float*)d_in[5];
    const float* node_w2  = (const float*)d_in[6];
    const float* node_b2  = (const float*)d_in[7];
    const float* coord_w1 = (const float*)d_in[8];
    const float* coord_b1 = (const float*)d_in[9];
    const float* coord_w2 = (const float*)d_in[10];
    const float* edge_w1  = (const float*)d_in[11];
    const float* edge_b1  = (const float*)d_in[12];
    const float* edge_w2  = (const float*)d_in[13];
    const float* edge_b2  = (const float*)d_in[14];
    float* out = (float*)d_out;

    (void)in_sizes; (void)n_in; (void)out_size;

    detect_kernel<<<1, 32>>>((const unsigned int*)eidx);
    convert_kernel<<<(N_EDGES + 255) / 256, 256>>>(eidx);

    const int total_out = N_NODES * ND + N_NODES * 3;
    init_out_kernel<<<(total_out + 255) / 256, 256>>>(h, x, out);

    const int smem_bytes =
        (MI * HD * 2 + HD * ND + ED * ED + HD * 3 + ND + ED * 3) * (int)sizeof(float);
    cudaFuncSetAttribute(edge_kernel,
                         cudaFuncAttributeMaxDynamicSharedMemorySize, smem_bytes);

    int nsm = 148;
    cudaDeviceGetAttribute(&nsm, cudaDevAttrMultiProcessorCount, 0);

    edge_kernel<<<nsm, THREADS, smem_bytes>>>(
        h, x, edist,
        node_w1, node_b1, node_w2, node_b2,
        coord_w1, coord_b1, coord_w2,
        edge_w1, edge_b1, edge_w2, edge_b2,
        out);
}